// round 3
// baseline (speedup 1.0000x reference)
#include <cuda_runtime.h>

#define HID  128
#define MH   64
#define D32  32
#define OUTD 128
#define NB   128   // blocks; 8 rows each; NB <= SM count so all co-resident

// ---- device globals (no allocation allowed). All reset each replay. ----
__device__ float         g_part[NB * 128]; // [b][0:64)=hid, [64:96)=a, [96:128)=c
__device__ float         g_final[192];     // [0:32)=S, [32:64)=T, [64:192)=K
__device__ int           g_cnt1;
__device__ int           g_cnt2;
__device__ volatile int  g_flag;

__global__ void __launch_bounds__(256) k_fused(
    const float* __restrict__ hs,
    const float* __restrict__ obs1,
    const float* __restrict__ obs,
    const float* __restrict__ W_sp,
    const float* __restrict__ b_sp,
    const float* __restrict__ W_vel,
    const float* __restrict__ b_vel,
    const float* __restrict__ W_hid,
    const float* __restrict__ b_hid,
    const float* __restrict__ W_out,
    const float* __restrict__ b_out,
    float* __restrict__ out)
{
    __shared__ float hsS[8][HID];     // 4 KB
    __shared__ float sa[8][D32];      // 1 KB
    __shared__ float sc[8][D32];      // 1 KB
    __shared__ float red[4][MH];      // 1 KB
    __shared__ float red2[2][128];    // 1 KB (reducer)
    __shared__ float hmS[MH];         // 256 B (reducer)
    __shared__ float kred[2][OUTD];   // 1 KB (reducer)
    __shared__ float SS[D32], TS[D32], KS[OUTD];
    __shared__ float f[8][MH];        // 2 KB
    __shared__ int   isLast;

    int b = blockIdx.x, t = threadIdx.x;
    int row0 = b * 8;

    // ================= Phase A: per-block partials =================
    #pragma unroll
    for (int x = t; x < 8 * HID; x += 256)
        hsS[x >> 7][x & 127] = hs[row0 * HID + x];

    {   // projections: thread -> (row = t>>5, d = t&31)
        int row = t >> 5, d = t & 31;
        int i = row0 + row;
        float2 oo = ((const float2*)obs)[i];
        float2 o1 = ((const float2*)obs1)[i];
        sa[row][d] = fmaf(oo.x, W_sp[d], oo.y * W_sp[D32 + d]);
        float vx = 4.f * (oo.x - o1.x), vy = 4.f * (oo.y - o1.y);
        sc[row][d] = fmaf(vx, W_vel[d], vy * W_vel[D32 + d]);
    }
    __syncthreads();

    {   // hidden GEMM: k = t&63, rg = t>>6 (4 row-groups x 2 rows)
        int k = t & 63, rg = t >> 6;
        float bk = b_hid[k];
        float a0 = bk, a1 = bk;
        #pragma unroll 8
        for (int c = 0; c < HID; c++) {
            float w = __ldg(&W_hid[c * MH + k]);     // coalesced
            a0 = fmaf(hsS[rg * 2][c],     w, a0);    // smem broadcast
            a1 = fmaf(hsS[rg * 2 + 1][c], w, a1);
        }
        red[rg][k] = fmaxf(fmaxf(a0, a1), 0.f);      // relu folded into max
    }
    __syncthreads();

    if (t < 64) {
        g_part[b * 128 + t] = fmaxf(fmaxf(red[0][t], red[1][t]),
                                    fmaxf(red[2][t], red[3][t]));
    } else if (t < 96) {
        int d = t - 64;
        float m = sa[0][d];
        #pragma unroll
        for (int r = 1; r < 8; r++) m = fmaxf(m, sa[r][d]);
        g_part[b * 128 + t] = m;
    } else if (t < 128) {
        int d = t - 96;
        float m = sc[0][d];
        #pragma unroll
        for (int r = 1; r < 8; r++) m = fmaxf(m, sc[r][d]);
        g_part[b * 128 + t] = m;
    }
    __threadfence();
    if (t == 0) isLast = (atomicAdd(&g_cnt1, 1) == NB - 1);
    __syncthreads();

    // ================= Reducer tail (last-arriving block only) =================
    if (isLast) {
        {   // reduce NB partials: (col = t&127) x (half = t>>7, 64 rows each)
            int col = t & 127, half = t >> 7;
            const float* p = g_part + half * (NB / 2) * 128 + col;
            float m = -3.4e38f;
            #pragma unroll 16
            for (int q = 0; q < NB / 2; q++)
                m = fmaxf(m, __ldcg(&p[q * 128]));
            red2[half][col] = m;
        }
        __syncthreads();
        if (t < 128) {
            float v = fmaxf(red2[0][t], red2[1][t]);
            if (t < 64)       hmS[t] = v;
            else if (t < 96)  g_final[t - 64]      = v + b_sp[t - 64];
            else              g_final[32 + t - 96] = v + b_vel[t - 96];
        }
        __syncthreads();
        {   // K[o] = b_out[o] + sum_k hm[k] * W_out[64+k][o]
            int o = t & 127, kh = t >> 7;
            float acc = 0.f;
            #pragma unroll 8
            for (int k = kh * 32; k < kh * 32 + 32; k++)
                acc = fmaf(hmS[k], __ldg(&W_out[(64 + k) * OUTD + o]), acc);
            kred[kh][o] = acc;
        }
        __syncthreads();
        if (t < 128)
            g_final[64 + t] = b_out[t] + kred[0][t] + kred[1][t];
        __threadfence();
        if (t == 0) g_flag = 1;
    }

    // ================= Grid sync =================
    if (t == 0) {
        while (g_flag == 0) { }
        // past the spin: safe to count toward reset
        if (atomicAdd(&g_cnt2, 1) == NB - 1) {
            g_cnt1 = 0; g_cnt2 = 0; g_flag = 0;   // deterministic replays
        }
    }
    __syncthreads();

    // ================= Phase C: output GEMM (d < 64 only) =================
    for (int x = t; x < 192; x += 256) {
        float v = __ldcg(&g_final[x]);            // bypass L1 (cross-SM producer)
        if (x < 32)       SS[x] = v;
        else if (x < 64)  TS[x - 32] = v;
        else              KS[x - 64] = v;
    }
    __syncthreads();

    #pragma unroll
    for (int s = 0; s < 2; s++) {                  // 512 slots = 8 rows x 64 d
        int slot = t + 256 * s;
        int row = slot >> 6, d = slot & 63;
        float val;
        if (d < D32) {
            val = fmaxf(SS[d] - sa[row][d], 0.f);  // a already in smem
        } else {
            int dd = d - D32;
            val = fmaxf(TS[dd] - sc[row][dd], 0.f);
        }
        f[row][d] = val;
    }
    __syncthreads();

    {   // out[i,o] = KS[o] + sum_{d<64} f[i][d] * W_out[d][o]
        int o = t & 127, rh = t >> 7;              // 2 groups x 4 rows
        float k0 = KS[o];
        float acc[4] = {k0, k0, k0, k0};
        #pragma unroll 8
        for (int d = 0; d < 64; d++) {
            float w = __ldg(&W_out[d * OUTD + o]); // L2-resident, coalesced
            #pragma unroll
            for (int r = 0; r < 4; r++)
                acc[r] = fmaf(f[rh * 4 + r][d], w, acc[r]);
        }
        #pragma unroll
        for (int r = 0; r < 4; r++)
            out[(row0 + rh * 4 + r) * OUTD + o] = acc[r];
    }
}

extern "C" void kernel_launch(void* const* d_in, const int* in_sizes, int n_in,
                              void* d_out, int out_size)
{
    const float* hs    = (const float*)d_in[0];
    const float* obs1  = (const float*)d_in[1];
    const float* obs   = (const float*)d_in[2];
    const float* W_sp  = (const float*)d_in[3];
    const float* b_sp  = (const float*)d_in[4];
    const float* W_vel = (const float*)d_in[5];
    const float* b_vel = (const float*)d_in[6];
    const float* W_hid = (const float*)d_in[7];
    const float* b_hid = (const float*)d_in[8];
    const float* W_out = (const float*)d_in[9];
    const float* b_out = (const float*)d_in[10];
    float* out = (float*)d_out;

    k_fused<<<NB, 256>>>(hs, obs1, obs, W_sp, b_sp, W_vel, b_vel,
                         W_hid, b_hid, W_out, b_out, out);
}

// round 4
// speedup vs baseline: 2.1128x; 2.1128x over previous
#include <cuda_runtime.h>

#define HID  128
#define MH   64
#define D32  32
#define OUTD 128
#define NB   128   // k1/k3 grid; 8 rows per block

// ---- device globals (no allocation allowed); fully overwritten each replay ----
__device__ float g_part[NB * 128]; // [b][0:64)=hid, [64:96)=a, [96:128)=c
__device__ float g_final[192];     // [0:32)=S, [32:64)=T, [64:192)=K

// ================= k1: per-block partial maxes =================
__global__ void __launch_bounds__(256) k1(
    const float* __restrict__ hs,
    const float* __restrict__ obs1,
    const float* __restrict__ obs,
    const float* __restrict__ W_sp,
    const float* __restrict__ W_vel,
    const float* __restrict__ W_hid,
    const float* __restrict__ b_hid)
{
    __shared__ float hsS[8][HID];   // 4 KB
    __shared__ float sa[8][D32];    // 1 KB
    __shared__ float sc[8][D32];    // 1 KB
    __shared__ float red[4][MH];    // 1 KB
    int b = blockIdx.x, t = threadIdx.x;
    int row0 = b * 8;

    #pragma unroll
    for (int x = t; x < 8 * HID; x += 256)
        hsS[x >> 7][x & 127] = hs[row0 * HID + x];

    {   // projections: row = t>>5, d = t&31
        int row = t >> 5, d = t & 31;
        int i = row0 + row;
        float2 oo = ((const float2*)obs)[i];
        float2 o1 = ((const float2*)obs1)[i];
        sa[row][d] = fmaf(oo.x, W_sp[d], oo.y * W_sp[D32 + d]);
        float vx = 4.f * (oo.x - o1.x), vy = 4.f * (oo.y - o1.y);
        sc[row][d] = fmaf(vx, W_vel[d], vy * W_vel[D32 + d]);
    }
    __syncthreads();

    {   // hidden GEMM: k = t&63, rg = t>>6 (4 groups x 2 rows), prefetched
        int k = t & 63, rg = t >> 6;
        const float* wp = W_hid + k;
        float bk = b_hid[k];
        float a0 = bk, a1 = bk;
        #pragma unroll
        for (int c0 = 0; c0 < HID; c0 += 8) {
            float w[8];
            #pragma unroll
            for (int j = 0; j < 8; j++) w[j] = __ldg(&wp[(c0 + j) * MH]);
            #pragma unroll
            for (int j = 0; j < 8; j++) {
                a0 = fmaf(hsS[rg * 2][c0 + j],     w[j], a0);
                a1 = fmaf(hsS[rg * 2 + 1][c0 + j], w[j], a1);
            }
        }
        red[rg][k] = fmaxf(fmaxf(a0, a1), 0.f);   // relu folded into max
    }
    __syncthreads();

    if (t < 64) {
        g_part[b * 128 + t] = fmaxf(fmaxf(red[0][t], red[1][t]),
                                    fmaxf(red[2][t], red[3][t]));
    } else if (t < 96) {
        int d = t - 64;
        float m = sa[0][d];
        #pragma unroll
        for (int r = 1; r < 8; r++) m = fmaxf(m, sa[r][d]);
        g_part[b * 128 + t] = m;
    } else if (t < 128) {
        int d = t - 96;
        float m = sc[0][d];
        #pragma unroll
        for (int r = 1; r < 8; r++) m = fmaxf(m, sc[r][d]);
        g_part[b * 128 + t] = m;
    }
}

// ================= kR: single block, 1024 threads: reduce + S,T,K =================
__global__ void __launch_bounds__(1024) kR(
    const float* __restrict__ b_sp,
    const float* __restrict__ b_vel,
    const float* __restrict__ W_out,
    const float* __restrict__ b_out)
{
    __shared__ float red[8][128];   // 4 KB
    __shared__ float hmS[MH];
    __shared__ float kred[8][OUTD]; // 4 KB
    int t = threadIdx.x;

    {   // 128 cols x 8 groups; each group reduces 16 partial rows (1 L2 wave)
        int col = t & 127, grp = t >> 7;
        const float* p = g_part + grp * 16 * 128 + col;
        float m = -3.4e38f;
        #pragma unroll
        for (int q = 0; q < 16; q++) m = fmaxf(m, p[q * 128]);
        red[grp][col] = m;
    }
    __syncthreads();
    if (t < 128) {
        float v = red[0][t];
        #pragma unroll
        for (int g = 1; g < 8; g++) v = fmaxf(v, red[g][t]);
        if (t < 64)       hmS[t] = v;
        else if (t < 96)  g_final[t - 64]      = v + b_sp[t - 64];
        else              g_final[32 + t - 96] = v + b_vel[t - 96];
    }
    __syncthreads();
    {   // K[o] = b_out[o] + sum_k hm[k]*W_out[64+k][o]; 8 k's per thread
        int o = t & 127, kh = t >> 7;
        float acc = 0.f;
        #pragma unroll
        for (int j = 0; j < 8; j++) {
            int k = kh * 8 + j;
            acc = fmaf(hmS[k], __ldg(&W_out[(64 + k) * OUTD + o]), acc);
        }
        kred[kh][o] = acc;
    }
    __syncthreads();
    if (t < 128) {
        float s = b_out[t];
        #pragma unroll
        for (int g = 0; g < 8; g++) s += kred[g][t];
        g_final[64 + t] = s;
    }
}

// ================= k3: consumer output GEMM (d < 64 only) =================
__global__ void __launch_bounds__(256) k3(
    const float* __restrict__ obs1,
    const float* __restrict__ obs,
    const float* __restrict__ W_sp,
    const float* __restrict__ W_vel,
    const float* __restrict__ W_out,
    float* __restrict__ out)
{
    __shared__ float SS[D32], TS[D32], KS[OUTD];
    __shared__ float f[8][MH];      // 2 KB
    int b = blockIdx.x, t = threadIdx.x;
    int row0 = b * 8;

    if (t < 192) {                  // L2-hit (L1 flushed at launch -> fresh)
        float v = g_final[t];
        if (t < 32)       SS[t] = v;
        else if (t < 64)  TS[t - 32] = v;
        else              KS[t - 64] = v;
    }
    __syncthreads();

    #pragma unroll
    for (int s = 0; s < 2; s++) {   // 512 slots = 8 rows x 64 d
        int slot = t + 256 * s;
        int row = slot >> 6, d = slot & 63;
        int i = row0 + row;
        float2 oo = ((const float2*)obs)[i];
        float val;
        if (d < D32) {
            float a = fmaf(oo.x, W_sp[d], oo.y * W_sp[D32 + d]);
            val = fmaxf(SS[d] - a, 0.f);
        } else {
            int dd = d - D32;
            float2 o1 = ((const float2*)obs1)[i];
            float vx = 4.f * (oo.x - o1.x), vy = 4.f * (oo.y - o1.y);
            float c = fmaf(vx, W_vel[dd], vy * W_vel[D32 + dd]);
            val = fmaxf(TS[dd] - c, 0.f);
        }
        f[row][d] = val;
    }
    __syncthreads();

    {   // out[i,o] = KS[o] + sum_{d<64} f[i][d]*W_out[d][o], prefetched 8-wide
        int o = t & 127, rh = t >> 7;   // 2 groups x 4 rows
        float k0 = KS[o];
        float acc[4] = {k0, k0, k0, k0};
        const float* wp = W_out + o;
        #pragma unroll
        for (int d0 = 0; d0 < 64; d0 += 8) {
            float w[8];
            #pragma unroll
            for (int j = 0; j < 8; j++) w[j] = __ldg(&wp[(d0 + j) * OUTD]);
            #pragma unroll
            for (int j = 0; j < 8; j++) {
                #pragma unroll
                for (int r = 0; r < 4; r++)
                    acc[r] = fmaf(f[rh * 4 + r][d0 + j], w[j], acc[r]);
            }
        }
        #pragma unroll
        for (int r = 0; r < 4; r++)
            out[(row0 + rh * 4 + r) * OUTD + o] = acc[r];
    }
}

extern "C" void kernel_launch(void* const* d_in, const int* in_sizes, int n_in,
                              void* d_out, int out_size)
{
    const float* hs    = (const float*)d_in[0];
    const float* obs1  = (const float*)d_in[1];
    const float* obs   = (const float*)d_in[2];
    const float* W_sp  = (const float*)d_in[3];
    const float* b_sp  = (const float*)d_in[4];
    const float* W_vel = (const float*)d_in[5];
    const float* b_vel = (const float*)d_in[6];
    const float* W_hid = (const float*)d_in[7];
    const float* b_hid = (const float*)d_in[8];
    const float* W_out = (const float*)d_in[9];
    const float* b_out = (const float*)d_in[10];
    float* out = (float*)d_out;

    k1<<<NB, 256>>>(hs, obs1, obs, W_sp, W_vel, W_hid, b_hid);
    kR<<<1, 1024>>>(b_sp, b_vel, W_out, b_out);
    k3<<<NB, 256>>>(obs1, obs, W_sp, W_vel, W_out, out);
}

// round 5
// speedup vs baseline: 2.3580x; 1.1160x over previous
#include <cuda_runtime.h>

#define HID  128
#define MH   64
#define D32  32
#define OUTD 128
#define NB   128   // k1/k3 grid; 8 rows per block

// ---- device globals (no allocation allowed); fully overwritten each replay ----
__device__ float g_part[NB * 128]; // [b][0:64)=hid, [64:96)=a, [96:128)=c
__device__ float g_final[192];     // [0:32)=S, [32:64)=T, [64:192)=K
__device__ float g_dummy[1024];    // sink for L2-warm prefetch

// ================= k1: per-block partial maxes (512 thr, c-split 2-way) ==========
__global__ void __launch_bounds__(512) k1(
    const float* __restrict__ hs,
    const float* __restrict__ obs1,
    const float* __restrict__ obs,
    const float* __restrict__ W_sp,
    const float* __restrict__ W_vel,
    const float* __restrict__ W_hid,
    const float* __restrict__ b_hid)
{
    __shared__ float hsS[8][HID];   // 4 KB
    __shared__ float sa[8][D32];    // 1 KB
    __shared__ float sc[8][D32];    // 1 KB
    __shared__ float p0[8][MH];     // 2 KB  partial sums, row even
    __shared__ float p1[8][MH];     // 2 KB  partial sums, row odd
    __shared__ float red[4][MH];    // 1 KB
    int b = blockIdx.x, t = threadIdx.x;
    int row0 = b * 8;

    if (t < 256) {                  // hs tile: 1024 floats as 256 float4 (1 wave)
        ((float4*)hsS)[t] = ((const float4*)(hs + row0 * HID))[t];
    } else {                        // projections: row = tt>>5, d = tt&31
        int tt = t - 256;
        int row = tt >> 5, d = tt & 31;
        int i = row0 + row;
        float2 oo = ((const float2*)obs)[i];
        float2 o1 = ((const float2*)obs1)[i];
        sa[row][d] = fmaf(oo.x, W_sp[d], oo.y * W_sp[D32 + d]);
        float vx = 4.f * (oo.x - o1.x), vy = 4.f * (oo.y - o1.y);
        sc[row][d] = fmaf(vx, W_vel[d], vy * W_vel[D32 + d]);
    }
    __syncthreads();

    {   // GEMM: 512 thr = k(64) x ch(2 c-halves) x rg(4 row-pairs); 8 batches/thr
        int k = t & 63, g = t >> 6;          // g = rg*2 + ch
        int ch = g & 1, rg = g >> 1;
        const float* wp = W_hid + ch * 64 * MH + k;
        const float* h0 = &hsS[rg * 2][ch * 64];
        const float* h1 = &hsS[rg * 2 + 1][ch * 64];
        float a0 = 0.f, a1 = 0.f;
        #pragma unroll
        for (int c0 = 0; c0 < 64; c0 += 8) {
            float w[8];
            #pragma unroll
            for (int j = 0; j < 8; j++) w[j] = __ldg(&wp[(c0 + j) * MH]);
            #pragma unroll
            for (int j = 0; j < 8; j++) {
                a0 = fmaf(h0[c0 + j], w[j], a0);
                a1 = fmaf(h1[c0 + j], w[j], a1);
            }
        }
        p0[g][k] = a0;
        p1[g][k] = a1;
    }
    __syncthreads();

    if (t < 256) {                  // combine c-halves, relu, max over 2 rows
        int k = t & 63, rg = t >> 6;
        float bk = b_hid[k];
        float a0 = bk + p0[rg * 2][k] + p0[rg * 2 + 1][k];
        float a1 = bk + p1[rg * 2][k] + p1[rg * 2 + 1][k];
        red[rg][k] = fmaxf(fmaxf(a0, a1), 0.f);
    }
    __syncthreads();

    if (t < 64) {
        g_part[b * 128 + t] = fmaxf(fmaxf(red[0][t], red[1][t]),
                                    fmaxf(red[2][t], red[3][t]));
    } else if (t < 96) {
        int d = t - 64;
        float m = sa[0][d];
        #pragma unroll
        for (int r = 1; r < 8; r++) m = fmaxf(m, sa[r][d]);
        g_part[b * 128 + t] = m;
    } else if (t < 128) {
        int d = t - 96;
        float m = sc[0][d];
        #pragma unroll
        for (int r = 1; r < 8; r++) m = fmaxf(m, sc[r][d]);
        g_part[b * 128 + t] = m;
    }
}

// ================= kR: 1 block x 1024 thr: reduce + S,T,K + L2 prefetch ==========
__global__ void __launch_bounds__(1024) kR(
    const float* __restrict__ b_sp,
    const float* __restrict__ b_vel,
    const float* __restrict__ W_out,
    const float* __restrict__ b_out)
{
    __shared__ float red[8][128];   // 4 KB
    __shared__ float hmS[MH];
    __shared__ float kred[8][OUTD]; // 4 KB
    int t = threadIdx.x;

    // L2-warm prefetch of W_out[0:64] (8192 floats, 8 coalesced loads/thread),
    // overlapped with the partial reduction below; sunk into g_dummy.
    float dummy = 0.f;
    #pragma unroll
    for (int j = 0; j < 8; j++) dummy += __ldg(&W_out[j * 1024 + t]);

    {   // 128 cols x 8 groups; each group reduces 16 partial rows (1 L2 wave)
        int col = t & 127, grp = t >> 7;
        const float* p = g_part + grp * 16 * 128 + col;
        float m = -3.4e38f;
        #pragma unroll
        for (int q = 0; q < 16; q++) m = fmaxf(m, p[q * 128]);
        red[grp][col] = m;
    }
    g_dummy[t] = dummy;
    __syncthreads();
    if (t < 128) {
        float v = red[0][t];
        #pragma unroll
        for (int g = 1; g < 8; g++) v = fmaxf(v, red[g][t]);
        if (t < 64)       hmS[t] = v;
        else if (t < 96)  g_final[t - 64]      = v + b_sp[t - 64];
        else              g_final[32 + t - 96] = v + b_vel[t - 96];
    }
    __syncthreads();
    {   // K[o] = b_out[o] + sum_k hm[k]*W_out[64+k][o]; 8 k's per thread
        int o = t & 127, kh = t >> 7;
        float acc = 0.f;
        #pragma unroll
        for (int j = 0; j < 8; j++) {
            int k = kh * 8 + j;
            acc = fmaf(hmS[k], __ldg(&W_out[(64 + k) * OUTD + o]), acc);
        }
        kred[kh][o] = acc;
    }
    __syncthreads();
    if (t < 128) {
        float s = b_out[t];
        #pragma unroll
        for (int g = 0; g < 8; g++) s += kred[g][t];
        g_final[64 + t] = s;
    }
}

// ================= k3: consumer output GEMM (512 thr, d-split 2-way) =============
__global__ void __launch_bounds__(512) k3(
    const float* __restrict__ obs1,
    const float* __restrict__ obs,
    const float* __restrict__ W_sp,
    const float* __restrict__ W_vel,
    const float* __restrict__ W_out,
    float* __restrict__ out)
{
    __shared__ float SS[D32], TS[D32], KS[OUTD];
    __shared__ float f[8][MH];        // 2 KB
    __shared__ float part[4][4][128]; // 8 KB [g][row_in_group][o]
    int b = blockIdx.x, t = threadIdx.x;
    int row0 = b * 8;

    if (t < 192) {
        float v = g_final[t];         // L2 hit (fresh L1 after launch)
        if (t < 32)       SS[t] = v;
        else if (t < 64)  TS[t - 32] = v;
        else              KS[t - 64] = v;
    }
    __syncthreads();

    {   // features: 512 slots = 8 rows x 64 d, one per thread
        int row = t >> 6, d = t & 63;
        int i = row0 + row;
        float2 oo = ((const float2*)obs)[i];
        float val;
        if (d < D32) {
            float a = fmaf(oo.x, W_sp[d], oo.y * W_sp[D32 + d]);
            val = fmaxf(SS[d] - a, 0.f);
        } else {
            int dd = d - D32;
            float2 o1 = ((const float2*)obs1)[i];
            float vx = 4.f * (oo.x - o1.x), vy = 4.f * (oo.y - o1.y);
            float c = fmaf(vx, W_vel[dd], vy * W_vel[D32 + dd]);
            val = fmaxf(TS[dd] - c, 0.f);
        }
        f[row][d] = val;
    }
    __syncthreads();

    {   // GEMM: 512 thr = o(128) x ch(2 d-halves) x rh(2 row-quads); 4 batches/thr
        int o = t & 127, g = t >> 7;  // g = rh*2 + ch
        int ch = g & 1, rh = g >> 1;
        const float* wp = W_out + ch * 32 * OUTD + o;
        float acc[4] = {0.f, 0.f, 0.f, 0.f};
        #pragma unroll
        for (int d0 = 0; d0 < 32; d0 += 8) {
            float w[8];
            #pragma unroll
            for (int j = 0; j < 8; j++) w[j] = __ldg(&wp[(d0 + j) * OUTD]);
            #pragma unroll
            for (int j = 0; j < 8; j++) {
                #pragma unroll
                for (int r = 0; r < 4; r++)
                    acc[r] = fmaf(f[rh * 4 + r][ch * 32 + d0 + j], w[j], acc[r]);
            }
        }
        #pragma unroll
        for (int r = 0; r < 4; r++) part[g][r][o] = acc[r];
    }
    __syncthreads();

    {   // combine d-halves + K, write out: 1024 outputs, 2 per thread
        #pragma unroll
        for (int s = 0; s < 2; s++) {
            int slot = t + 512 * s;
            int row = slot >> 7, o = slot & 127;
            int rh = row >> 2, r = row & 3;
            out[(row0 + row) * OUTD + o] =
                KS[o] + part[rh * 2][r][o] + part[rh * 2 + 1][r][o];
        }
    }
}

extern "C" void kernel_launch(void* const* d_in, const int* in_sizes, int n_in,
                              void* d_out, int out_size)
{
    const float* hs    = (const float*)d_in[0];
    const float* obs1  = (const float*)d_in[1];
    const float* obs   = (const float*)d_in[2];
    const float* W_sp  = (const float*)d_in[3];
    const float* b_sp  = (const float*)d_in[4];
    const float* W_vel = (const float*)d_in[5];
    const float* b_vel = (const float*)d_in[6];
    const float* W_hid = (const float*)d_in[7];
    const float* b_hid = (const float*)d_in[8];
    const float* W_out = (const float*)d_in[9];
    const float* b_out = (const float*)d_in[10];
    float* out = (float*)d_out;

    k1<<<NB, 512>>>(hs, obs1, obs, W_sp, W_vel, W_hid, b_hid);
    kR<<<1, 1024>>>(b_sp, b_vel, W_out, b_out);
    k3<<<NB, 512>>>(obs1, obs, W_sp, W_vel, W_out, out);
}